// round 9
// baseline (speedup 1.0000x reference)
#include <cuda_runtime.h>
#include <cstdint>

#define N_NODES 100000
#define N_EDGES 1600000
#define D 64
#define SCAN_BLOCKS 98   // ceil(100000/1024)

// Scratch (no cudaMalloc allowed).
__device__ float g_dinv[N_NODES];
__device__ float g_xw1[N_NODES * D];
__device__ int   g_cnt[N_NODES];
__device__ int   g_offs[N_NODES + 1];
__device__ int   g_cursor[N_NODES];
__device__ int2  g_srt[N_EDGES];
__device__ int   g_bsum[SCAN_BLOCKS];
__device__ int   g_idx64;

__device__ __forceinline__ int load_idx(const long long* ei64,
                                        const int* ei32, int is64,
                                        long long pos) {
    return is64 ? (int)ei64[pos] : ei32[pos];
}

// ---------------------------------------------------------------------------
// K0: zero deg + cnt; thread 0 detects edge_index dtype (int64 indices < 2^31
// LE have every odd 32-bit word == 0).
__global__ void k_init(const int* __restrict__ ei32) {
    int i = blockIdx.x * blockDim.x + threadIdx.x;
    if (i < N_NODES) {
        g_dinv[i] = 0.0f;
        g_cnt[i] = 0;
    }
    if (i == 0) {
        int all_zero = 1;
        for (int j = 1; j < 128; j += 2)
            if (ei32[j] != 0) all_zero = 0;
        g_idx64 = all_zero;
    }
}

// K1: single edge pass: deg[row] += w  and  cnt[col] += 1
__global__ __launch_bounds__(256) void k_edge1(const long long* __restrict__ ei64,
                                               const int* __restrict__ ei32,
                                               const float* __restrict__ w) {
    int e = blockIdx.x * blockDim.x + threadIdx.x;
    if (e >= N_EDGES) return;
    int is64 = g_idx64;
    int row = load_idx(ei64, ei32, is64, e);
    int col = load_idx(ei64, ei32, is64, (long long)e + N_EDGES);
    if ((unsigned)row < N_NODES) atomicAdd(&g_dinv[row], w[e]);
    if ((unsigned)col < N_NODES) atomicAdd(&g_cnt[col], 1);
}

// ---------------------------------------------------------------------------
// Scan step 1: per-block sums of cnt (1024 elems per block). Also finalizes
// dinv = deg > 0 ? rsqrt(deg) : 0 (folded in; same index range).
__global__ __launch_bounds__(1024) void k_scan1() {
    __shared__ int sh[1024];
    int t = threadIdx.x;
    int i = blockIdx.x * 1024 + t;
    if (i < N_NODES) {
        float d = g_dinv[i];
        g_dinv[i] = (d > 0.0f) ? rsqrtf(d) : 0.0f;
    }
    sh[t] = (i < N_NODES) ? g_cnt[i] : 0;
    __syncthreads();
    for (int s = 512; s > 0; s >>= 1) {
        if (t < s) sh[t] += sh[t + s];
        __syncthreads();
    }
    if (t == 0) g_bsum[blockIdx.x] = sh[0];
}

// Scan step 2: exclusive scan of block sums.
__global__ void k_scan2() {
    __shared__ int sh[SCAN_BLOCKS];
    int t = threadIdx.x;
    if (t < SCAN_BLOCKS) sh[t] = g_bsum[t];
    __syncthreads();
    if (t == 0) {
        int run = 0;
        for (int j = 0; j < SCAN_BLOCKS; j++) {
            int v = sh[j];
            g_bsum[j] = run;
            run += v;
        }
        g_offs[N_NODES] = run;
    }
}

// Scan step 3: per-block inclusive scan -> exclusive offsets + cursor copy.
__global__ __launch_bounds__(1024) void k_scan3() {
    __shared__ int sh[1024];
    int t = threadIdx.x;
    int i = blockIdx.x * 1024 + t;
    int own = (i < N_NODES) ? g_cnt[i] : 0;
    sh[t] = own;
    __syncthreads();
    for (int s = 1; s < 1024; s <<= 1) {
        int v = (t >= s) ? sh[t - s] : 0;
        __syncthreads();
        sh[t] += v;
        __syncthreads();
    }
    if (i < N_NODES) {
        int excl = sh[t] - own + g_bsum[blockIdx.x];
        g_offs[i] = excl;
        g_cursor[i] = excl;
    }
}

// K-place: bucket each edge into its col segment; precompute norm.
__global__ __launch_bounds__(256) void k_place(const long long* __restrict__ ei64,
                                               const int* __restrict__ ei32,
                                               const float* __restrict__ w) {
    int e = blockIdx.x * blockDim.x + threadIdx.x;
    if (e >= N_EDGES) return;
    int is64 = g_idx64;
    int row = load_idx(ei64, ei32, is64, e);
    int col = load_idx(ei64, ei32, is64, (long long)e + N_EDGES);
    if ((unsigned)row >= N_NODES || (unsigned)col >= N_NODES) return;
    float norm = -g_dinv[row] * w[e] * g_dinv[col];
    int pos = atomicAdd(&g_cursor[col], 1);
    g_srt[pos] = make_int2(row, __float_as_int(norm));
}

// ---------------------------------------------------------------------------
// K-gemm (R6 known-good version): out = x @ W0 + b ;  g_xw1 = x @ W1
// W0/W1 staged in shared once per block; blocks stride over node tiles
// (4 nodes per tile, 64 threads per node).
__global__ __launch_bounds__(256) void k_gemm(const float* __restrict__ x,
                                              const float* __restrict__ W0,
                                              const float* __restrict__ W1,
                                              const float* __restrict__ b,
                                              float* __restrict__ out) {
    __shared__ float sW0[D * D];
    __shared__ float sW1[D * D];
    __shared__ float sb[D];
    __shared__ float sx[4][D];

    int tid = threadIdx.x;
    for (int i = tid; i < D * D; i += 256) {
        sW0[i] = W0[i];
        sW1[i] = W1[i];
    }
    if (tid < D) sb[tid] = b[tid];
    __syncthreads();

    int tx = tid & 63;   // output column
    int ty = tid >> 6;   // node within tile (0..3)

    const int ntiles = N_NODES / 4;
    for (int tile = blockIdx.x; tile < ntiles; tile += gridDim.x) {
        int node = tile * 4 + ty;
        sx[ty][tx] = x[node * D + tx];
        __syncthreads();

        float a0 = 0.0f, a1 = 0.0f;
#pragma unroll
        for (int k = 0; k < D; k++) {
            float xv = sx[ty][k];
            a0 = fmaf(xv, sW0[k * D + tx], a0);
            a1 = fmaf(xv, sW1[k * D + tx], a1);
        }
        out[node * D + tx]   = a0 + sb[tx];
        g_xw1[node * D + tx] = a1;
        __syncthreads();
    }
}

// ---------------------------------------------------------------------------
// K-spmm: one warp per destination column; no atomics.
// srt stream software-pipelined 2-deep so the gather never waits on the
// same-iteration srt load.
__global__ __launch_bounds__(256) void k_spmm(float* __restrict__ out) {
    int gw = (blockIdx.x * blockDim.x + threadIdx.x) >> 5;
    if (gw >= N_NODES) return;
    int lane = threadIdx.x & 31;

    int start = g_offs[gw];
    int end   = g_offs[gw + 1];

    int2 a0 = make_int2(0, 0), a1 = make_int2(0, 0);
    if (start < end)     a0 = __ldg(&g_srt[start]);
    if (start + 1 < end) a1 = __ldg(&g_srt[start + 1]);

    float ax = 0.0f, ay = 0.0f;
    for (int i = start; i < end; i++) {
        int2 cur = a0;
        a0 = a1;
        if (i + 2 < end) a1 = __ldg(&g_srt[i + 2]);

        float norm = __int_as_float(cur.y);
        const float2 v =
            *reinterpret_cast<const float2*>(&g_xw1[cur.x * D + lane * 2]);
        ax = fmaf(norm, v.x, ax);
        ay = fmaf(norm, v.y, ay);
    }

    float2* o = reinterpret_cast<float2*>(&out[gw * D + lane * 2]);
    float2 curo = *o;
    curo.x += ax;
    curo.y += ay;
    *o = curo;
}

// ---------------------------------------------------------------------------
extern "C" void kernel_launch(void* const* d_in, const int* in_sizes, int n_in,
                              void* d_out, int out_size) {
    // Bind inputs by element count (unambiguous for this problem).
    const float* x  = nullptr;
    const void*  ei = nullptr;
    const float* w  = nullptr;
    const float* W0 = nullptr;
    const float* W1 = nullptr;
    const float* b  = nullptr;
    for (int i = 0; i < n_in; i++) {
        long long n = in_sizes[i];
        if (n == (long long)N_NODES * D)      x  = (const float*)d_in[i];
        else if (n == 2LL * N_EDGES)          ei = d_in[i];
        else if (n == (long long)N_EDGES)     w  = (const float*)d_in[i];
        else if (n == D * D) { if (!W0) W0 = (const float*)d_in[i];
                               else     W1 = (const float*)d_in[i]; }
        else if (n == D)                      b  = (const float*)d_in[i];
    }
    const long long* ei64 = (const long long*)ei;
    const int*       ei32 = (const int*)ei;
    float* out = (float*)d_out;

    k_init<<<(N_NODES + 255) / 256, 256>>>(ei32);
    k_edge1<<<(N_EDGES + 255) / 256, 256>>>(ei64, ei32, w);
    k_scan1<<<SCAN_BLOCKS, 1024>>>();
    k_scan2<<<1, 128>>>();
    k_scan3<<<SCAN_BLOCKS, 1024>>>();
    k_place<<<(N_EDGES + 255) / 256, 256>>>(ei64, ei32, w);
    k_gemm<<<592, 256>>>(x, W0, W1, b, out);

    // one warp per column
    k_spmm<<<(N_NODES * 32 + 255) / 256, 256>>>(out);
}

// round 11
// speedup vs baseline: 1.0135x; 1.0135x over previous
#include <cuda_runtime.h>
#include <cstdint>

#define N_NODES 100000
#define N_EDGES 1600000
#define D 64

// Scratch (no cudaMalloc allowed).
__device__ float g_dinv[N_NODES];            // degree -> dinv in place
__device__ float g_xw1[N_NODES * D];         // x @ W1
__device__ int   g_cnt[N_NODES];             // col histogram
__device__ int   g_offs[N_NODES + 1];        // CSR offsets (exclusive scan)
__device__ int   g_cursor[N_NODES];          // placement cursors
__device__ int2  g_srt[N_EDGES];             // sorted {row, norm_bits}
__device__ int   g_bsum[128];                // per-block scan sums
__device__ int   g_idx64;                    // 1 if edge_index is int64

#define SCAN_BLOCKS 98                        // ceil(100000/1024)

__device__ __forceinline__ int load_idx(const long long* ei64,
                                        const int* ei32, int is64,
                                        long long pos) {
    return is64 ? (int)ei64[pos] : ei32[pos];
}

// ---------------------------------------------------------------------------
// K0: zero deg + cnt; block 0 / thread 0 also detects edge_index dtype.
// int64 indices < 2^31 (LE) have every odd 32-bit word == 0.
__global__ void k_init(const int* __restrict__ ei32) {
    int i = blockIdx.x * blockDim.x + threadIdx.x;
    if (i < N_NODES) {
        g_dinv[i] = 0.0f;
        g_cnt[i] = 0;
    }
    if (i == 0) {
        int all_zero = 1;
        for (int j = 1; j < 128; j += 2)
            if (ei32[j] != 0) all_zero = 0;
        g_idx64 = all_zero;
    }
}

// K1: single edge pass: deg[row] += w  and  cnt[col] += 1
__global__ __launch_bounds__(256) void k_edge1(const long long* __restrict__ ei64,
                                               const int* __restrict__ ei32,
                                               const float* __restrict__ w) {
    int e = blockIdx.x * blockDim.x + threadIdx.x;
    if (e >= N_EDGES) return;
    int is64 = g_idx64;
    int row = load_idx(ei64, ei32, is64, e);
    int col = load_idx(ei64, ei32, is64, (long long)e + N_EDGES);
    if ((unsigned)row < N_NODES) atomicAdd(&g_dinv[row], w[e]);
    if ((unsigned)col < N_NODES) atomicAdd(&g_cnt[col], 1);
}

// K2: dinv = deg > 0 ? rsqrt(deg) : 0
__global__ void k_dinv() {
    int i = blockIdx.x * blockDim.x + threadIdx.x;
    if (i < N_NODES) {
        float d = g_dinv[i];
        g_dinv[i] = (d > 0.0f) ? rsqrtf(d) : 0.0f;
    }
}

// ---------------------------------------------------------------------------
// Scan step 1: per-block sums of cnt (1024 elems per block)
__global__ __launch_bounds__(1024) void k_scan1() {
    __shared__ int sh[1024];
    int t = threadIdx.x;
    int i = blockIdx.x * 1024 + t;
    sh[t] = (i < N_NODES) ? g_cnt[i] : 0;
    __syncthreads();
    for (int s = 512; s > 0; s >>= 1) {
        if (t < s) sh[t] += sh[t + s];
        __syncthreads();
    }
    if (t == 0) g_bsum[blockIdx.x] = sh[0];
}

// Scan step 2: exclusive scan of block sums; also writes offs[N] = total.
__global__ void k_scan2() {
    __shared__ int sh[SCAN_BLOCKS];
    int t = threadIdx.x;
    if (t < SCAN_BLOCKS) sh[t] = g_bsum[t];
    __syncthreads();
    if (t == 0) {
        int run = 0;
        for (int j = 0; j < SCAN_BLOCKS; j++) {
            int v = sh[j];
            g_bsum[j] = run;
            run += v;
        }
        g_offs[N_NODES] = run;
    }
}

// Scan step 3: per-block inclusive scan -> exclusive offsets + cursor copy.
__global__ __launch_bounds__(1024) void k_scan3() {
    __shared__ int sh[1024];
    int t = threadIdx.x;
    int i = blockIdx.x * 1024 + t;
    int own = (i < N_NODES) ? g_cnt[i] : 0;
    sh[t] = own;
    __syncthreads();
    for (int s = 1; s < 1024; s <<= 1) {
        int v = (t >= s) ? sh[t - s] : 0;
        __syncthreads();
        sh[t] += v;
        __syncthreads();
    }
    if (i < N_NODES) {
        int excl = sh[t] - own + g_bsum[blockIdx.x];
        g_offs[i] = excl;
        g_cursor[i] = excl;
    }
}

// K-place: bucket each edge into its col segment; precompute norm.
__global__ __launch_bounds__(256) void k_place(const long long* __restrict__ ei64,
                                               const int* __restrict__ ei32,
                                               const float* __restrict__ w) {
    int e = blockIdx.x * blockDim.x + threadIdx.x;
    if (e >= N_EDGES) return;
    int is64 = g_idx64;
    int row = load_idx(ei64, ei32, is64, e);
    int col = load_idx(ei64, ei32, is64, (long long)e + N_EDGES);
    if ((unsigned)row >= N_NODES || (unsigned)col >= N_NODES) return;
    float norm = -g_dinv[row] * w[e] * g_dinv[col];
    int pos = atomicAdd(&g_cursor[col], 1);
    g_srt[pos] = make_int2(row, __float_as_int(norm));
}

// ---------------------------------------------------------------------------
// K-gemm: out = x @ W0 + b ;  g_xw1 = x @ W1
__global__ __launch_bounds__(256) void k_gemm(const float* __restrict__ x,
                                              const float* __restrict__ W0,
                                              const float* __restrict__ W1,
                                              const float* __restrict__ b,
                                              float* __restrict__ out) {
    __shared__ float sW0[D * D];
    __shared__ float sW1[D * D];
    __shared__ float sb[D];
    __shared__ float sx[4][D];

    int tid = threadIdx.x;
    for (int i = tid; i < D * D; i += 256) {
        sW0[i] = W0[i];
        sW1[i] = W1[i];
    }
    if (tid < D) sb[tid] = b[tid];
    __syncthreads();

    int tx = tid & 63;   // output column
    int ty = tid >> 6;   // node within tile (0..3)

    const int ntiles = N_NODES / 4;
    for (int tile = blockIdx.x; tile < ntiles; tile += gridDim.x) {
        int node = tile * 4 + ty;
        sx[ty][tx] = x[node * D + tx];
        __syncthreads();

        float a0 = 0.0f, a1 = 0.0f;
#pragma unroll
        for (int k = 0; k < D; k++) {
            float xv = sx[ty][k];
            a0 = fmaf(xv, sW0[k * D + tx], a0);
            a1 = fmaf(xv, sW1[k * D + tx], a1);
        }
        out[node * D + tx]   = a0 + sb[tx];
        g_xw1[node * D + tx] = a1;
        __syncthreads();
    }
}

// ---------------------------------------------------------------------------
// K-spmm: one warp per destination column; no atomics.
// out[col, :] += sum_e norm_e * xw1[row_e, :]
__global__ __launch_bounds__(256) void k_spmm(float* __restrict__ out) {
    int gw = (blockIdx.x * blockDim.x + threadIdx.x) >> 5;
    if (gw >= N_NODES) return;
    int lane = threadIdx.x & 31;

    int start = g_offs[gw];
    int end   = g_offs[gw + 1];

    float ax = 0.0f, ay = 0.0f;
    for (int i = start; i < end; i++) {
        int2 rn = __ldg(&g_srt[i]);            // warp-uniform broadcast
        int   row  = rn.x;
        float norm = __int_as_float(rn.y);
        const float2 v =
            *reinterpret_cast<const float2*>(&g_xw1[row * D + lane * 2]);
        ax = fmaf(norm, v.x, ax);
        ay = fmaf(norm, v.y, ay);
    }

    float2* o = reinterpret_cast<float2*>(&out[gw * D + lane * 2]);
    float2 cur = *o;
    cur.x += ax;
    cur.y += ay;
    *o = cur;
}

// ---------------------------------------------------------------------------
extern "C" void kernel_launch(void* const* d_in, const int* in_sizes, int n_in,
                              void* d_out, int out_size) {
    // Bind inputs by element count (unambiguous for this problem).
    const float* x  = nullptr;
    const void*  ei = nullptr;
    const float* w  = nullptr;
    const float* W0 = nullptr;
    const float* W1 = nullptr;
    const float* b  = nullptr;
    for (int i = 0; i < n_in; i++) {
        long long n = in_sizes[i];
        if (n == (long long)N_NODES * D)      x  = (const float*)d_in[i];
        else if (n == 2LL * N_EDGES)          ei = d_in[i];
        else if (n == (long long)N_EDGES)     w  = (const float*)d_in[i];
        else if (n == D * D) { if (!W0) W0 = (const float*)d_in[i];
                               else     W1 = (const float*)d_in[i]; }
        else if (n == D)                      b  = (const float*)d_in[i];
    }
    const long long* ei64 = (const long long*)ei;
    const int*       ei32 = (const int*)ei;
    float* out = (float*)d_out;

    k_init<<<(N_NODES + 255) / 256, 256>>>(ei32);
    k_edge1<<<(N_EDGES + 255) / 256, 256>>>(ei64, ei32, w);
    k_dinv<<<(N_NODES + 255) / 256, 256>>>();
    k_scan1<<<SCAN_BLOCKS, 1024>>>();
    k_scan2<<<1, 128>>>();
    k_scan3<<<SCAN_BLOCKS, 1024>>>();
    k_place<<<(N_EDGES + 255) / 256, 256>>>(ei64, ei32, w);
    k_gemm<<<592, 256>>>(x, W0, W1, b, out);

    // one warp per column
    k_spmm<<<(N_NODES * 32 + 255) / 256, 256>>>(out);
}

// round 12
// speedup vs baseline: 1.5703x; 1.5493x over previous
#include <cuda_runtime.h>
#include <cuda_fp16.h>
#include <cstdint>

#define N_NODES 100000
#define N_EDGES 1600000
#define D 64
#define SCAN_BLOCKS 98   // ceil(100000/1024)

// Scratch (no cudaMalloc allowed).
__device__ float  g_dinv[N_NODES];            // degree -> dinv in place
__device__ __half g_xw1h[N_NODES * D];        // x @ W1, fp16 (halves gather traffic)
__device__ int    g_cnt[N_NODES];             // col histogram
__device__ int    g_offs[N_NODES + 1];        // CSR offsets (exclusive scan)
__device__ int    g_cursor[N_NODES];          // placement cursors
__device__ int2   g_srt[N_EDGES];             // sorted {row, norm_bits}
__device__ int    g_bsum[SCAN_BLOCKS];        // per-block scan sums
__device__ int    g_idx64;                    // 1 if edge_index is int64

__device__ __forceinline__ int load_idx(const long long* ei64,
                                        const int* ei32, int is64,
                                        long long pos) {
    return is64 ? (int)ei64[pos] : ei32[pos];
}

// ---------------------------------------------------------------------------
// K0: zero deg + cnt; thread 0 detects edge_index dtype (int64 indices < 2^31
// LE have every odd 32-bit word == 0).
__global__ void k_init(const int* __restrict__ ei32) {
    int i = blockIdx.x * blockDim.x + threadIdx.x;
    if (i < N_NODES) {
        g_dinv[i] = 0.0f;
        g_cnt[i] = 0;
    }
    if (i == 0) {
        int all_zero = 1;
        for (int j = 1; j < 128; j += 2)
            if (ei32[j] != 0) all_zero = 0;
        g_idx64 = all_zero;
    }
}

// K1: single edge pass: deg[row] += w  and  cnt[col] += 1
__global__ __launch_bounds__(256) void k_edge1(const long long* __restrict__ ei64,
                                               const int* __restrict__ ei32,
                                               const float* __restrict__ w) {
    int e = blockIdx.x * blockDim.x + threadIdx.x;
    if (e >= N_EDGES) return;
    int is64 = g_idx64;
    int row = load_idx(ei64, ei32, is64, e);
    int col = load_idx(ei64, ei32, is64, (long long)e + N_EDGES);
    if ((unsigned)row < N_NODES) atomicAdd(&g_dinv[row], w[e]);
    if ((unsigned)col < N_NODES) atomicAdd(&g_cnt[col], 1);
}

// ---------------------------------------------------------------------------
// Scan step 1: per-block sums of cnt (1024 elems per block). Also finalizes
// dinv = deg > 0 ? rsqrt(deg) : 0 (same index range, folded in).
__global__ __launch_bounds__(1024) void k_scan1() {
    __shared__ int sh[1024];
    int t = threadIdx.x;
    int i = blockIdx.x * 1024 + t;
    if (i < N_NODES) {
        float d = g_dinv[i];
        g_dinv[i] = (d > 0.0f) ? rsqrtf(d) : 0.0f;
    }
    sh[t] = (i < N_NODES) ? g_cnt[i] : 0;
    __syncthreads();
    for (int s = 512; s > 0; s >>= 1) {
        if (t < s) sh[t] += sh[t + s];
        __syncthreads();
    }
    if (t == 0) g_bsum[blockIdx.x] = sh[0];
}

// Scan step 2: exclusive scan of block sums; also writes offs[N] = total.
__global__ void k_scan2() {
    __shared__ int sh[SCAN_BLOCKS];
    int t = threadIdx.x;
    if (t < SCAN_BLOCKS) sh[t] = g_bsum[t];
    __syncthreads();
    if (t == 0) {
        int run = 0;
        for (int j = 0; j < SCAN_BLOCKS; j++) {
            int v = sh[j];
            g_bsum[j] = run;
            run += v;
        }
        g_offs[N_NODES] = run;
    }
}

// Scan step 3: per-block inclusive scan -> exclusive offsets + cursor copy.
__global__ __launch_bounds__(1024) void k_scan3() {
    __shared__ int sh[1024];
    int t = threadIdx.x;
    int i = blockIdx.x * 1024 + t;
    int own = (i < N_NODES) ? g_cnt[i] : 0;
    sh[t] = own;
    __syncthreads();
    for (int s = 1; s < 1024; s <<= 1) {
        int v = (t >= s) ? sh[t - s] : 0;
        __syncthreads();
        sh[t] += v;
        __syncthreads();
    }
    if (i < N_NODES) {
        int excl = sh[t] - own + g_bsum[blockIdx.x];
        g_offs[i] = excl;
        g_cursor[i] = excl;
    }
}

// K-place: bucket each edge into its col segment; precompute norm.
__global__ __launch_bounds__(256) void k_place(const long long* __restrict__ ei64,
                                               const int* __restrict__ ei32,
                                               const float* __restrict__ w) {
    int e = blockIdx.x * blockDim.x + threadIdx.x;
    if (e >= N_EDGES) return;
    int is64 = g_idx64;
    int row = load_idx(ei64, ei32, is64, e);
    int col = load_idx(ei64, ei32, is64, (long long)e + N_EDGES);
    if ((unsigned)row >= N_NODES || (unsigned)col >= N_NODES) return;
    float norm = -g_dinv[row] * w[e] * g_dinv[col];
    int pos = atomicAdd(&g_cursor[col], 1);
    g_srt[pos] = make_int2(row, __float_as_int(norm));
}

// ---------------------------------------------------------------------------
// K-gemm: out = x @ W0 + b ;  g_xw1h = half(x @ W1)
// W0/W1 staged in shared once per block; blocks stride over node tiles
// (4 nodes per tile, 64 threads per node).
__global__ __launch_bounds__(256) void k_gemm(const float* __restrict__ x,
                                              const float* __restrict__ W0,
                                              const float* __restrict__ W1,
                                              const float* __restrict__ b,
                                              float* __restrict__ out) {
    __shared__ float sW0[D * D];
    __shared__ float sW1[D * D];
    __shared__ float sb[D];
    __shared__ float sx[4][D];

    int tid = threadIdx.x;
    for (int i = tid; i < D * D; i += 256) {
        sW0[i] = W0[i];
        sW1[i] = W1[i];
    }
    if (tid < D) sb[tid] = b[tid];
    __syncthreads();

    int tx = tid & 63;   // output column
    int ty = tid >> 6;   // node within tile (0..3)

    const int ntiles = N_NODES / 4;
    for (int tile = blockIdx.x; tile < ntiles; tile += gridDim.x) {
        int node = tile * 4 + ty;
        sx[ty][tx] = x[node * D + tx];
        __syncthreads();

        float a0 = 0.0f, a1 = 0.0f;
#pragma unroll
        for (int k = 0; k < D; k++) {
            float xv = sx[ty][k];
            a0 = fmaf(xv, sW0[k * D + tx], a0);
            a1 = fmaf(xv, sW1[k * D + tx], a1);
        }
        out[node * D + tx]   = a0 + sb[tx];
        g_xw1h[node * D + tx] = __float2half(a1);
        __syncthreads();
    }
}

// ---------------------------------------------------------------------------
// K-spmm: one warp per destination column; no atomics.
// out[col, :] += sum_e norm_e * xw1[row_e, :]
// fp16 row gather: 32 lanes x half2 = exactly one 128B line per edge.
__global__ __launch_bounds__(256) void k_spmm(float* __restrict__ out) {
    int gw = (blockIdx.x * blockDim.x + threadIdx.x) >> 5;
    if (gw >= N_NODES) return;
    int lane = threadIdx.x & 31;

    int start = g_offs[gw];
    int end   = g_offs[gw + 1];

    const __half2* xw1h2 = reinterpret_cast<const __half2*>(g_xw1h);

    float ax = 0.0f, ay = 0.0f;
    for (int i = start; i < end; i++) {
        int2 rn = __ldg(&g_srt[i]);            // warp-uniform broadcast
        int   row  = rn.x;
        float norm = __int_as_float(rn.y);
        float2 v = __half22float2(__ldg(&xw1h2[row * 32 + lane]));
        ax = fmaf(norm, v.x, ax);
        ay = fmaf(norm, v.y, ay);
    }

    float2* o = reinterpret_cast<float2*>(&out[gw * D + lane * 2]);
    float2 cur = *o;
    cur.x += ax;
    cur.y += ay;
    *o = cur;
}

// ---------------------------------------------------------------------------
extern "C" void kernel_launch(void* const* d_in, const int* in_sizes, int n_in,
                              void* d_out, int out_size) {
    // Bind inputs by element count (unambiguous for this problem).
    const float* x  = nullptr;
    const void*  ei = nullptr;
    const float* w  = nullptr;
    const float* W0 = nullptr;
    const float* W1 = nullptr;
    const float* b  = nullptr;
    for (int i = 0; i < n_in; i++) {
        long long n = in_sizes[i];
        if (n == (long long)N_NODES * D)      x  = (const float*)d_in[i];
        else if (n == 2LL * N_EDGES)          ei = d_in[i];
        else if (n == (long long)N_EDGES)     w  = (const float*)d_in[i];
        else if (n == D * D) { if (!W0) W0 = (const float*)d_in[i];
                               else     W1 = (const float*)d_in[i]; }
        else if (n == D)                      b  = (const float*)d_in[i];
    }
    const long long* ei64 = (const long long*)ei;
    const int*       ei32 = (const int*)ei;
    float* out = (float*)d_out;

    k_init<<<(N_NODES + 255) / 256, 256>>>(ei32);
    k_edge1<<<(N_EDGES + 255) / 256, 256>>>(ei64, ei32, w);
    k_scan1<<<SCAN_BLOCKS, 1024>>>();
    k_scan2<<<1, 128>>>();
    k_scan3<<<SCAN_BLOCKS, 1024>>>();
    k_place<<<(N_EDGES + 255) / 256, 256>>>(ei64, ei32, w);
    k_gemm<<<592, 256>>>(x, W0, W1, b, out);

    // one warp per column
    k_spmm<<<(N_NODES * 32 + 255) / 256, 256>>>(out);
}

// round 13
// speedup vs baseline: 1.6237x; 1.0340x over previous
#include <cuda_runtime.h>
#include <cuda_fp16.h>
#include <cstdint>

#define N_NODES 100000
#define N_EDGES 1600000
#define D 64
#define SCAN_BLOCKS 98   // ceil(100000/1024)

// Scratch (no cudaMalloc allowed).
__device__ float  g_dinv[N_NODES];            // degree -> dinv in place
__device__ __half g_xw1h[N_NODES * D];        // dinv[row] * (x @ W1)[row,:], fp16
__device__ int    g_cnt[N_NODES];             // col histogram
__device__ int    g_offs[N_NODES + 1];        // CSR offsets (exclusive scan)
__device__ int    g_cursor[N_NODES];          // placement cursors
__device__ int2   g_srt[N_EDGES];             // sorted {row, w_bits}
__device__ int    g_bsum[SCAN_BLOCKS];        // per-block scan sums
__device__ int    g_idx64;                    // 1 if edge_index is int64

__device__ __forceinline__ int load_idx(const long long* ei64,
                                        const int* ei32, int is64,
                                        long long pos) {
    return is64 ? (int)ei64[pos] : ei32[pos];
}

// ---------------------------------------------------------------------------
// K0: zero deg + cnt; thread 0 detects edge_index dtype (int64 indices < 2^31
// LE have every odd 32-bit word == 0).
__global__ void k_init(const int* __restrict__ ei32) {
    int i = blockIdx.x * blockDim.x + threadIdx.x;
    if (i < N_NODES) {
        g_dinv[i] = 0.0f;
        g_cnt[i] = 0;
    }
    if (i == 0) {
        int all_zero = 1;
        for (int j = 1; j < 128; j += 2)
            if (ei32[j] != 0) all_zero = 0;
        g_idx64 = all_zero;
    }
}

// K1: single edge pass: deg[row] += w  and  cnt[col] += 1
__global__ __launch_bounds__(256) void k_edge1(const long long* __restrict__ ei64,
                                               const int* __restrict__ ei32,
                                               const float* __restrict__ w) {
    int e = blockIdx.x * blockDim.x + threadIdx.x;
    if (e >= N_EDGES) return;
    int is64 = g_idx64;
    int row = load_idx(ei64, ei32, is64, e);
    int col = load_idx(ei64, ei32, is64, (long long)e + N_EDGES);
    if ((unsigned)row < N_NODES) atomicAdd(&g_dinv[row], w[e]);
    if ((unsigned)col < N_NODES) atomicAdd(&g_cnt[col], 1);
}

// ---------------------------------------------------------------------------
// Scan step 1: per-block sums of cnt (1024 elems per block). Also finalizes
// dinv = deg > 0 ? rsqrt(deg) : 0 (same index range, folded in).
__global__ __launch_bounds__(1024) void k_scan1() {
    __shared__ int sh[1024];
    int t = threadIdx.x;
    int i = blockIdx.x * 1024 + t;
    if (i < N_NODES) {
        float d = g_dinv[i];
        g_dinv[i] = (d > 0.0f) ? rsqrtf(d) : 0.0f;
    }
    sh[t] = (i < N_NODES) ? g_cnt[i] : 0;
    __syncthreads();
    for (int s = 512; s > 0; s >>= 1) {
        if (t < s) sh[t] += sh[t + s];
        __syncthreads();
    }
    if (t == 0) g_bsum[blockIdx.x] = sh[0];
}

// Scan step 2: exclusive scan of block sums; also writes offs[N] = total.
__global__ void k_scan2() {
    __shared__ int sh[SCAN_BLOCKS];
    int t = threadIdx.x;
    if (t < SCAN_BLOCKS) sh[t] = g_bsum[t];
    __syncthreads();
    if (t == 0) {
        int run = 0;
        for (int j = 0; j < SCAN_BLOCKS; j++) {
            int v = sh[j];
            g_bsum[j] = run;
            run += v;
        }
        g_offs[N_NODES] = run;
    }
}

// Scan step 3: per-block inclusive scan -> exclusive offsets + cursor copy.
__global__ __launch_bounds__(1024) void k_scan3() {
    __shared__ int sh[1024];
    int t = threadIdx.x;
    int i = blockIdx.x * 1024 + t;
    int own = (i < N_NODES) ? g_cnt[i] : 0;
    sh[t] = own;
    __syncthreads();
    for (int s = 1; s < 1024; s <<= 1) {
        int v = (t >= s) ? sh[t - s] : 0;
        __syncthreads();
        sh[t] += v;
        __syncthreads();
    }
    if (i < N_NODES) {
        int excl = sh[t] - own + g_bsum[blockIdx.x];
        g_offs[i] = excl;
        g_cursor[i] = excl;
    }
}

// K-place: bucket each edge into its col segment. NO dinv gathers — stores
// raw {row, w}; the dinv factors are folded into k_gemm (dinv[row]) and the
// k_spmm epilogue (dinv[col]).
__global__ __launch_bounds__(256) void k_place(const long long* __restrict__ ei64,
                                               const int* __restrict__ ei32,
                                               const float* __restrict__ w) {
    int e = blockIdx.x * blockDim.x + threadIdx.x;
    if (e >= N_EDGES) return;
    int is64 = g_idx64;
    int row = load_idx(ei64, ei32, is64, e);
    int col = load_idx(ei64, ei32, is64, (long long)e + N_EDGES);
    if ((unsigned)row >= N_NODES || (unsigned)col >= N_NODES) return;
    int pos = atomicAdd(&g_cursor[col], 1);
    g_srt[pos] = make_int2(row, __float_as_int(w[e]));
}

// ---------------------------------------------------------------------------
// K-gemm: out = x @ W0 + b ;  g_xw1h = half(dinv[node] * (x @ W1))
// W0/W1 staged in shared once per block; blocks stride over node tiles
// (4 nodes per tile, 64 threads per node).
__global__ __launch_bounds__(256) void k_gemm(const float* __restrict__ x,
                                              const float* __restrict__ W0,
                                              const float* __restrict__ W1,
                                              const float* __restrict__ b,
                                              float* __restrict__ out) {
    __shared__ float sW0[D * D];
    __shared__ float sW1[D * D];
    __shared__ float sb[D];
    __shared__ float sx[4][D];

    int tid = threadIdx.x;
    for (int i = tid; i < D * D; i += 256) {
        sW0[i] = W0[i];
        sW1[i] = W1[i];
    }
    if (tid < D) sb[tid] = b[tid];
    __syncthreads();

    int tx = tid & 63;   // output column
    int ty = tid >> 6;   // node within tile (0..3)

    const int ntiles = N_NODES / 4;
    for (int tile = blockIdx.x; tile < ntiles; tile += gridDim.x) {
        int node = tile * 4 + ty;
        sx[ty][tx] = x[node * D + tx];
        float dv = g_dinv[node];       // broadcast load (uniform per 64 threads)
        __syncthreads();

        float a0 = 0.0f, a1 = 0.0f;
#pragma unroll
        for (int k = 0; k < D; k++) {
            float xv = sx[ty][k];
            a0 = fmaf(xv, sW0[k * D + tx], a0);
            a1 = fmaf(xv, sW1[k * D + tx], a1);
        }
        out[node * D + tx]    = a0 + sb[tx];
        g_xw1h[node * D + tx] = __float2half(a1 * dv);
        __syncthreads();
    }
}

// ---------------------------------------------------------------------------
// K-spmm: one warp per destination column; no atomics.
// out[col, :] += -dinv[col] * sum_e w_e * (dinv[row]*xw1[row, :])
// fp16 row gather: 32 lanes x half2 = exactly one 128B line per edge.
__global__ __launch_bounds__(256) void k_spmm(float* __restrict__ out) {
    int gw = (blockIdx.x * blockDim.x + threadIdx.x) >> 5;
    if (gw >= N_NODES) return;
    int lane = threadIdx.x & 31;

    int start = g_offs[gw];
    int end   = g_offs[gw + 1];

    const __half2* xw1h2 = reinterpret_cast<const __half2*>(g_xw1h);

    float ax = 0.0f, ay = 0.0f;
    for (int i = start; i < end; i++) {
        int2 rn = __ldg(&g_srt[i]);            // warp-uniform broadcast
        int   row = rn.x;
        float we  = __int_as_float(rn.y);
        float2 v = __half22float2(__ldg(&xw1h2[row * 32 + lane]));
        ax = fmaf(we, v.x, ax);
        ay = fmaf(we, v.y, ay);
    }

    float ndc = -g_dinv[gw];                   // warp-uniform

    float2* o = reinterpret_cast<float2*>(&out[gw * D + lane * 2]);
    float2 cur = *o;
    cur.x = fmaf(ndc, ax, cur.x);
    cur.y = fmaf(ndc, ay, cur.y);
    *o = cur;
}

// ---------------------------------------------------------------------------
extern "C" void kernel_launch(void* const* d_in, const int* in_sizes, int n_in,
                              void* d_out, int out_size) {
    // Bind inputs by element count (unambiguous for this problem).
    const float* x  = nullptr;
    const void*  ei = nullptr;
    const float* w  = nullptr;
    const float* W0 = nullptr;
    const float* W1 = nullptr;
    const float* b  = nullptr;
    for (int i = 0; i < n_in; i++) {
        long long n = in_sizes[i];
        if (n == (long long)N_NODES * D)      x  = (const float*)d_in[i];
        else if (n == 2LL * N_EDGES)          ei = d_in[i];
        else if (n == (long long)N_EDGES)     w  = (const float*)d_in[i];
        else if (n == D * D) { if (!W0) W0 = (const float*)d_in[i];
                               else     W1 = (const float*)d_in[i]; }
        else if (n == D)                      b  = (const float*)d_in[i];
    }
    const long long* ei64 = (const long long*)ei;
    const int*       ei32 = (const int*)ei;
    float* out = (float*)d_out;

    k_init<<<(N_NODES + 255) / 256, 256>>>(ei32);
    k_edge1<<<(N_EDGES + 255) / 256, 256>>>(ei64, ei32, w);
    k_scan1<<<SCAN_BLOCKS, 1024>>>();
    k_scan2<<<1, 128>>>();
    k_scan3<<<SCAN_BLOCKS, 1024>>>();
    k_place<<<(N_EDGES + 255) / 256, 256>>>(ei64, ei32, w);
    k_gemm<<<592, 256>>>(x, W0, W1, b, out);

    // one warp per column
    k_spmm<<<(N_NODES * 32 + 255) / 256, 256>>>(out);
}

// round 15
// speedup vs baseline: 1.7748x; 1.0930x over previous
#include <cuda_runtime.h>
#include <cuda_fp16.h>
#include <cstdint>

#define N_NODES 100000
#define N_EDGES 1600000
#define D 64
#define SCAN_BLOCKS 98   // ceil(100000/1024)

// Scratch (no cudaMalloc allowed).
__device__ float  g_dinv[N_NODES];            // degree -> dinv in place
__device__ __half g_xw1h[N_NODES * D];        // dinv[row] * (x @ W1)[row,:], fp16
__device__ int    g_cnt[N_NODES];             // col histogram
__device__ int    g_offs[N_NODES + 1];        // CSR offsets (exclusive scan)
__device__ int    g_cursor[N_NODES];          // placement cursors
__device__ int2   g_srt[N_EDGES];             // sorted {row, w_bits}
__device__ int    g_bsum[SCAN_BLOCKS];        // per-block scan sums
__device__ int    g_idx64;                    // 1 if edge_index is int64

__device__ __forceinline__ int load_idx(const long long* ei64,
                                        const int* ei32, int is64,
                                        long long pos) {
    return is64 ? (int)ei64[pos] : ei32[pos];
}

// ---------------------------------------------------------------------------
// K0: zero deg + cnt; thread 0 detects edge_index dtype (int64 indices < 2^31
// LE have every odd 32-bit word == 0).
__global__ void k_init(const int* __restrict__ ei32) {
    int i = blockIdx.x * blockDim.x + threadIdx.x;
    if (i < N_NODES) {
        g_dinv[i] = 0.0f;
        g_cnt[i] = 0;
    }
    if (i == 0) {
        int all_zero = 1;
        for (int j = 1; j < 128; j += 2)
            if (ei32[j] != 0) all_zero = 0;
        g_idx64 = all_zero;
    }
}

// K1: single edge pass: deg[row] += w  and  cnt[col] += 1
__global__ __launch_bounds__(256) void k_edge1(const long long* __restrict__ ei64,
                                               const int* __restrict__ ei32,
                                               const float* __restrict__ w) {
    int e = blockIdx.x * blockDim.x + threadIdx.x;
    if (e >= N_EDGES) return;
    int is64 = g_idx64;
    int row = load_idx(ei64, ei32, is64, e);
    int col = load_idx(ei64, ei32, is64, (long long)e + N_EDGES);
    if ((unsigned)row < N_NODES) atomicAdd(&g_dinv[row], w[e]);
    if ((unsigned)col < N_NODES) atomicAdd(&g_cnt[col], 1);
}

// ---------------------------------------------------------------------------
// Scan step 1: per-block sums of cnt (1024 elems per block). Also finalizes
// dinv = deg > 0 ? rsqrt(deg) : 0 (same index range, folded in).
__global__ __launch_bounds__(1024) void k_scan1() {
    __shared__ int sh[1024];
    int t = threadIdx.x;
    int i = blockIdx.x * 1024 + t;
    if (i < N_NODES) {
        float d = g_dinv[i];
        g_dinv[i] = (d > 0.0f) ? rsqrtf(d) : 0.0f;
    }
    sh[t] = (i < N_NODES) ? g_cnt[i] : 0;
    __syncthreads();
    for (int s = 512; s > 0; s >>= 1) {
        if (t < s) sh[t] += sh[t + s];
        __syncthreads();
    }
    if (t == 0) g_bsum[blockIdx.x] = sh[0];
}

// Scan step 2: exclusive scan of block sums; also writes offs[N] = total.
__global__ void k_scan2() {
    __shared__ int sh[SCAN_BLOCKS];
    int t = threadIdx.x;
    if (t < SCAN_BLOCKS) sh[t] = g_bsum[t];
    __syncthreads();
    if (t == 0) {
        int run = 0;
        for (int j = 0; j < SCAN_BLOCKS; j++) {
            int v = sh[j];
            g_bsum[j] = run;
            run += v;
        }
        g_offs[N_NODES] = run;
    }
}

// Scan step 3: per-block inclusive scan -> exclusive offsets + cursor copy.
__global__ __launch_bounds__(1024) void k_scan3() {
    __shared__ int sh[1024];
    int t = threadIdx.x;
    int i = blockIdx.x * 1024 + t;
    int own = (i < N_NODES) ? g_cnt[i] : 0;
    sh[t] = own;
    __syncthreads();
    for (int s = 1; s < 1024; s <<= 1) {
        int v = (t >= s) ? sh[t - s] : 0;
        __syncthreads();
        sh[t] += v;
        __syncthreads();
    }
    if (i < N_NODES) {
        int excl = sh[t] - own + g_bsum[blockIdx.x];
        g_offs[i] = excl;
        g_cursor[i] = excl;
    }
}

// K-place: bucket each edge into its col segment. NO dinv gathers — stores
// raw {row, w}; the dinv factors are folded into k_gemm (dinv[row]) and the
// k_spmm epilogue (dinv[col]).
__global__ __launch_bounds__(256) void k_place(const long long* __restrict__ ei64,
                                               const int* __restrict__ ei32,
                                               const float* __restrict__ w) {
    int e = blockIdx.x * blockDim.x + threadIdx.x;
    if (e >= N_EDGES) return;
    int is64 = g_idx64;
    int row = load_idx(ei64, ei32, is64, e);
    int col = load_idx(ei64, ei32, is64, (long long)e + N_EDGES);
    if ((unsigned)row >= N_NODES || (unsigned)col >= N_NODES) return;
    int pos = atomicAdd(&g_cursor[col], 1);
    g_srt[pos] = make_int2(row, __float_as_int(w[e]));
}

// ---------------------------------------------------------------------------
// K-gemm: out = x @ W0 + b ;  g_xw1h = half(dinv[node] * (x @ W1))
// 256 threads = 8 warps; one node per warp per tile; lane owns a column PAIR.
// Weights staged in shared as float2 (LDS.64 per access) -> per k-step a warp
// does 2x LDS.64 + 1/4 LDS.128 (x broadcast) + 4 FFMA: FMA-bound, not LDS-bound.
__global__ __launch_bounds__(256) void k_gemm(const float* __restrict__ x,
                                              const float* __restrict__ W0,
                                              const float* __restrict__ W1,
                                              const float* __restrict__ b,
                                              float* __restrict__ out) {
    __shared__ float2 sW0[D * 32];   // [k][col_pair]
    __shared__ float2 sW1[D * 32];
    __shared__ float2 sb2[32];
    __shared__ float  sx[8][D];
    __shared__ float  sdv[8];

    int t = threadIdx.x;
    const float2* W0f2 = reinterpret_cast<const float2*>(W0);
    const float2* W1f2 = reinterpret_cast<const float2*>(W1);
    for (int i = t; i < D * 32; i += 256) {
        sW0[i] = W0f2[i];
        sW1[i] = W1f2[i];
    }
    if (t < 32) sb2[t] = reinterpret_cast<const float2*>(b)[t];
    __syncthreads();

    int c2 = t & 31;   // column pair (cols 2*c2, 2*c2+1)
    int ny = t >> 5;   // node within tile == warp id (x broadcast warp-uniform)

    const int ntiles = N_NODES / 8;   // 12500
    for (int tile = blockIdx.x; tile < ntiles; tile += gridDim.x) {
        int base = tile * 8;
#pragma unroll
        for (int j = t; j < 8 * D; j += 256)
            sx[j >> 6][j & 63] = x[(base + (j >> 6)) * D + (j & 63)];
        if (t < 8) sdv[t] = g_dinv[base + t];
        __syncthreads();

        float2 a0 = make_float2(0.f, 0.f);
        float2 a1 = make_float2(0.f, 0.f);
#pragma unroll
        for (int k = 0; k < D; k++) {
            float  xv = sx[ny][k];
            float2 w0 = sW0[k * 32 + c2];
            float2 w1 = sW1[k * 32 + c2];
            a0.x = fmaf(xv, w0.x, a0.x);
            a0.y = fmaf(xv, w0.y, a0.y);
            a1.x = fmaf(xv, w1.x, a1.x);
            a1.y = fmaf(xv, w1.y, a1.y);
        }

        int node = base + ny;
        float2 bb = sb2[c2];
        reinterpret_cast<float2*>(out)[node * 32 + c2] =
            make_float2(a0.x + bb.x, a0.y + bb.y);
        float dv = sdv[ny];
        reinterpret_cast<__half2*>(g_xw1h)[node * 32 + c2] =
            __floats2half2_rn(a1.x * dv, a1.y * dv);
        __syncthreads();
    }
}

// ---------------------------------------------------------------------------
// K-spmm: one warp per destination column; no atomics.
// out[col, :] += -dinv[col] * sum_e w_e * (dinv[row]*xw1[row, :])
// fp16 row gather: 32 lanes x half2 = exactly one 128B line per edge.
__global__ __launch_bounds__(256) void k_spmm(float* __restrict__ out) {
    int gw = (blockIdx.x * blockDim.x + threadIdx.x) >> 5;
    if (gw >= N_NODES) return;
    int lane = threadIdx.x & 31;

    int start = g_offs[gw];
    int end   = g_offs[gw + 1];

    const __half2* xw1h2 = reinterpret_cast<const __half2*>(g_xw1h);

    float ax = 0.0f, ay = 0.0f;
    for (int i = start; i < end; i++) {
        int2 rn = __ldg(&g_srt[i]);            // warp-uniform broadcast
        int   row = rn.x;
        float we  = __int_as_float(rn.y);
        float2 v = __half22float2(__ldg(&xw1h2[row * 32 + lane]));
        ax = fmaf(we, v.x, ax);
        ay = fmaf(we, v.y, ay);
    }

    float ndc = -g_dinv[gw];                   // warp-uniform

    float2* o = reinterpret_cast<float2*>(&out[gw * D + lane * 2]);
    float2 cur = *o;
    cur.x = fmaf(ndc, ax, cur.x);
    cur.y = fmaf(ndc, ay, cur.y);
    *o = cur;
}

// ---------------------------------------------------------------------------
extern "C" void kernel_launch(void* const* d_in, const int* in_sizes, int n_in,
                              void* d_out, int out_size) {
    // Bind inputs by element count (unambiguous for this problem).
    const float* x  = nullptr;
    const void*  ei = nullptr;
    const float* w  = nullptr;
    const float* W0 = nullptr;
    const float* W1 = nullptr;
    const float* b  = nullptr;
    for (int i = 0; i < n_in; i++) {
        long long n = in_sizes[i];
        if (n == (long long)N_NODES * D)      x  = (const float*)d_in[i];
        else if (n == 2LL * N_EDGES)          ei = d_in[i];
        else if (n == (long long)N_EDGES)     w  = (const float*)d_in[i];
        else if (n == D * D) { if (!W0) W0 = (const float*)d_in[i];
                               else     W1 = (const float*)d_in[i]; }
        else if (n == D)                      b  = (const float*)d_in[i];
    }
    const long long* ei64 = (const long long*)ei;
    const int*       ei32 = (const int*)ei;
    float* out = (float*)d_out;

    k_init<<<(N_NODES + 255) / 256, 256>>>(ei32);
    k_edge1<<<(N_EDGES + 255) / 256, 256>>>(ei64, ei32, w);
    k_scan1<<<SCAN_BLOCKS, 1024>>>();
    k_scan2<<<1, 128>>>();
    k_scan3<<<SCAN_BLOCKS, 1024>>>();
    k_place<<<(N_EDGES + 255) / 256, 256>>>(ei64, ei32, w);
    k_gemm<<<592, 256>>>(x, W0, W1, b, out);

    // one warp per column
    k_spmm<<<(N_NODES * 32 + 255) / 256, 256>>>(out);
}